// round 3
// baseline (speedup 1.0000x reference)
#include <cuda_runtime.h>
#include <cstdint>

// RVQ: x[B,S,768] f32, codebook[3,16,256] f32, alpha scalar.
// score(code) = x·k - 0.5||k||^2 ; argmax == argmin of squared distance.
// out = alpha*x + (1-alpha)*k[best]; code = b0 + 16*b1 + 256*b2 (stored as f32).

typedef unsigned long long u64;

#define NH 3
#define NC 16
#define DFULL 768
#define DHD 256
#define NF4 64          // float4 per code row
#define TPW 6           // tokens per warp pass
#define NWARP 8
#define THREADS 256
#define FULLM 0xffffffffu

__device__ __forceinline__ u64 f2fma(u64 a, u64 b, u64 c) {
    u64 d; asm("fma.rn.f32x2 %0,%1,%2,%3;" : "=l"(d) : "l"(a), "l"(b), "l"(c));
    return d;
}
__device__ __forceinline__ u64 f2add(u64 a, u64 b) {
    u64 d; asm("add.rn.f32x2 %0,%1,%2;" : "=l"(d) : "l"(a), "l"(b));
    return d;
}
__device__ __forceinline__ u64 f2mul(u64 a, u64 b) {
    u64 d; asm("mul.rn.f32x2 %0,%1,%2;" : "=l"(d) : "l"(a), "l"(b));
    return d;
}
__device__ __forceinline__ u64 bcast2(float x) {
    u64 d; unsigned b = __float_as_uint(x);
    asm("mov.b64 %0,{%1,%1};" : "=l"(d) : "r"(b));
    return d;
}
__device__ __forceinline__ float2 unpk(u64 d) {
    unsigned lo, hi;
    asm("mov.b64 {%0,%1},%2;" : "=r"(lo), "=r"(hi) : "l"(d));
    return make_float2(__uint_as_float(lo), __uint_as_float(hi));
}

__global__ void __launch_bounds__(THREADS, 2) rvq_kernel(
    const float* __restrict__ x,
    const float* __restrict__ cb,
    const float* __restrict__ alphap,
    float* __restrict__ out,
    float* __restrict__ code_out,
    int tokens, int write_code, int nwt)
{
    // Codebook, linear layout. Strided lane->dim mapping is conflict-free
    // without swizzle (bank group = 4*s mod 32, distinct per 8-lane phase).
    __shared__ ulonglong2 scb[NH * NC * NF4];   // 49152 B
    {
        const ulonglong2* c2 = (const ulonglong2*)cb;
        #pragma unroll
        for (int i = threadIdx.x; i < NH * NC * NF4; i += THREADS) scb[i] = c2[i];
    }
    __syncthreads();

    const int lane = threadIdx.x & 31;
    const int warp = threadIdx.x >> 5;
    const int g = lane >> 3;        // code group: codes 4g..4g+3
    const int s = lane & 7;         // dim slice: float4 indices s, s+8, ..., s+56
    const int mycode = 4 * g + 2 * (s & 1) + ((s >> 1) & 1);  // code after reduce

    const float4* scbf = (const float4*)scb;

    // Half squared norm of this lane's final code, per head (one-time).
    float hn[NH];
    #pragma unroll
    for (int h = 0; h < NH; h++) {
        const float4* row = scbf + (h * NC + mycode) * NF4;
        float t = 0.f;
        #pragma unroll
        for (int i = 0; i < NF4; i++) {
            float4 k = row[(i + mycode) & 63];
            t = fmaf(k.x, k.x, t); t = fmaf(k.y, k.y, t);
            t = fmaf(k.z, k.z, t); t = fmaf(k.w, k.w, t);
        }
        hn[h] = 0.5f * t;
    }

    const float alpha = *alphap;
    const u64 a2 = bcast2(alpha);
    const u64 b2 = bcast2(1.0f - alpha);

    for (int tile = blockIdx.x * NWARP + warp; tile < nwt; tile += gridDim.x * NWARP) {
        int t0 = tile * TPW;
        if (t0 > tokens - TPW) t0 = tokens - TPW;   // overlap tail: identical writes
        if (t0 < 0) t0 = 0;

        int pack[TPW];
        #pragma unroll
        for (int t = 0; t < TPW; t++) pack[t] = 0;

        #pragma unroll
        for (int h = 0; h < NH; h++) {
            // x base for this lane's dim slice; all further offsets are constants.
            const ulonglong2* xb =
                (const ulonglong2*)(x + (size_t)t0 * DFULL + h * DHD + s * 4);

            u64 acc[TPW][4];
            #pragma unroll
            for (int t = 0; t < TPW; t++) {
                acc[t][0] = 0ull; acc[t][1] = 0ull;
                acc[t][2] = 0ull; acc[t][3] = 0ull;
            }

            const ulonglong2* ks = scb + (h * NC + 4 * g) * NF4 + s;

            #pragma unroll
            for (int j = 0; j < 8; j++) {
                ulonglong2 k0 = ks[0 * NF4 + 8 * j];
                ulonglong2 k1 = ks[1 * NF4 + 8 * j];
                ulonglong2 k2 = ks[2 * NF4 + 8 * j];
                ulonglong2 k3 = ks[3 * NF4 + 8 * j];
                #pragma unroll
                for (int t = 0; t < TPW; t++) {
                    ulonglong2 xv = xb[t * 192 + 8 * j];   // t*768 + j*32 floats
                    acc[t][0] = f2fma(xv.x, k0.x, acc[t][0]);
                    acc[t][1] = f2fma(xv.x, k1.x, acc[t][1]);
                    acc[t][2] = f2fma(xv.x, k2.x, acc[t][2]);
                    acc[t][3] = f2fma(xv.x, k3.x, acc[t][3]);
                    acc[t][0] = f2fma(xv.y, k0.y, acc[t][0]);
                    acc[t][1] = f2fma(xv.y, k1.y, acc[t][1]);
                    acc[t][2] = f2fma(xv.y, k2.y, acc[t][2]);
                    acc[t][3] = f2fma(xv.y, k3.y, acc[t][3]);
                }
            }

            // Reduce over 8 dim-lanes (xor 1,2,4) with packed adds, then
            // REDUX argmax over the 16 codes spread across lanes.
            #pragma unroll
            for (int t = 0; t < TPW; t++) {
                const bool bit0 = (s & 1) != 0;
                u64 snd0 = bit0 ? acc[t][0] : acc[t][2];
                u64 kp0  = bit0 ? acc[t][2] : acc[t][0];
                u64 snd1 = bit0 ? acc[t][1] : acc[t][3];
                u64 kp1  = bit0 ? acc[t][3] : acc[t][1];
                u64 w0 = f2add(kp0, __shfl_xor_sync(FULLM, snd0, 1));
                u64 w1 = f2add(kp1, __shfl_xor_sync(FULLM, snd1, 1));

                const bool bit1 = (s & 2) != 0;
                u64 snd2 = bit1 ? w0 : w1;
                u64 kp2  = bit1 ? w1 : w0;
                u64 w = f2add(kp2, __shfl_xor_sync(FULLM, snd2, 2));

                w = f2add(w, __shfl_xor_sync(FULLM, w, 4));   // duplicate halves

                float2 p = unpk(w);
                float sc = p.x + p.y - hn[h];

                // monotone map fp32 -> u32, redux max, then min-code tiebreak
                int bb = __float_as_int(sc);
                unsigned u = (unsigned)(bb ^ ((bb >> 31) | 0x80000000));
                unsigned umax = __reduce_max_sync(FULLM, u);
                unsigned cand = (u == umax) ? (unsigned)mycode : 64u;
                int bi = (int)__reduce_min_sync(FULLM, cand);
                pack[t] += bi << (4 * h);

                // Blend + store: cooperative layout, lane l handles float4 l, l+32.
                const ulonglong2* krow = scb + (h * NC + bi) * NF4;
                ulonglong2 kA = krow[lane];
                ulonglong2 kB = krow[lane + 32];
                const ulonglong2* xr =
                    (const ulonglong2*)(x + (size_t)(t0 + t) * DFULL + h * DHD) + lane;
                ulonglong2 xA = xr[0];
                ulonglong2 xB = xr[32];
                ulonglong2 oA, oB;
                oA.x = f2fma(a2, xA.x, f2mul(b2, kA.x));
                oA.y = f2fma(a2, xA.y, f2mul(b2, kA.y));
                oB.x = f2fma(a2, xB.x, f2mul(b2, kB.x));
                oB.y = f2fma(a2, xB.y, f2mul(b2, kB.y));
                ulonglong2* orow =
                    (ulonglong2*)(out + (size_t)(t0 + t) * DFULL + h * DHD) + lane;
                orow[0]  = oA;
                orow[32] = oB;
            }
        }

        if (write_code && lane == 0) {
            #pragma unroll
            for (int t = 0; t < TPW; t++)
                code_out[t0 + t] = (float)pack[t];
        }
    }
}

extern "C" void kernel_launch(void* const* d_in, const int* in_sizes, int n_in,
                              void* d_out, int out_size)
{
    const float* x      = (const float*)d_in[0];
    const float* kernel = (const float*)d_in[1];
    const float* alpha  = (const float*)d_in[2];
    float* out = (float*)d_out;

    const int tokens = in_sizes[0] / DFULL;
    const int nwt = (tokens + TPW - 1) / TPW;

    const long long out_elems = (long long)tokens * DFULL;
    int write_code = (out_size >= out_elems + tokens) ? 1 : 0;
    float* code_out = out + out_elems;

    int grid = (nwt + NWARP - 1) / NWARP;
    if (grid > 296) grid = 296;   // 2 resident blocks/SM * 148

    rvq_kernel<<<grid, THREADS>>>(x, kernel, alpha, out, code_out,
                                  tokens, write_code, nwt);
}

// round 5
// speedup vs baseline: 1.4390x; 1.4390x over previous
#include <cuda_runtime.h>
#include <cstdint>

// RVQ: x[B,S,768] f32, codebook[3,16,256] f32, alpha scalar.
// Per token, per head: argmax_{c<16} (x·k_c - 0.5||k_c||^2)  (== argmin dist)
// out = alpha*x + (1-alpha)*k[best]; code = b0 + 16*b1 + 256*b2 (as f32).
//
// 2-warp teams: both warps share 6 tokens; warp half owns codes 8*half..8*half+7.
// Cross-half argmax combined via u64 keys in smem + team-scoped named barrier.

typedef unsigned long long u64;

#define NH 3
#define NC 16
#define DFULL 768
#define DHD 256
#define TPT 6              // tokens per team pass
#define THREADS 256        // 8 warps = 4 teams
#define NTEAMS 4
#define FULLM 0xffffffffu

__device__ __forceinline__ unsigned fmono(float f) {
    int b = __float_as_int(f);
    return (unsigned)(b ^ ((b >> 31) | 0x80000000));
}

__global__ void __launch_bounds__(THREADS, 2) rvq_kernel(
    const float* __restrict__ x,
    const float* __restrict__ cb,
    const float* __restrict__ alphap,
    float* __restrict__ out,
    float* __restrict__ code_out,
    int tokens, int write_code, int nteamtiles)
{
    __shared__ float4 scb[NH * NC * 64];          // 48 KB codebook
    __shared__ u64 keys[2][8][TPT][NH];           // [parity][warp][t][h]

    {
        const float4* c4 = (const float4*)cb;
        #pragma unroll
        for (int i = threadIdx.x; i < NH * NC * 64; i += THREADS) scb[i] = c4[i];
    }
    __syncthreads();

    const int lane = threadIdx.x & 31;
    const int warp = threadIdx.x >> 5;
    const int team = warp >> 1;
    const int half = warp & 1;
    const int bar_id = 1 + team;

    // local code owned by this lane after split-exchange (bits 16,8,4)
    const int lcode = (((lane >> 4) & 1) << 2) | (((lane >> 3) & 1) << 1) | ((lane >> 2) & 1);
    const int gcode = half * 8 + lcode;

    // one-time: 0.5*||k[gcode]||^2 per head (rotated start to soften conflicts)
    float hn[NH];
    #pragma unroll
    for (int h = 0; h < NH; h++) {
        const float4* row = scb + (h * NC + gcode) * 64;
        float s = 0.f;
        #pragma unroll
        for (int i = 0; i < 64; i++) {
            float4 k = row[(i + 4 * gcode) & 63];
            s = fmaf(k.x, k.x, s); s = fmaf(k.y, k.y, s);
            s = fmaf(k.z, k.z, s); s = fmaf(k.w, k.w, s);
        }
        hn[h] = 0.5f * s;
    }

    const float alpha = *alphap;
    const float beta  = 1.0f - alpha;

    int parity = 0;
    for (int tile = blockIdx.x * NTEAMS + team; tile < nteamtiles;
         tile += gridDim.x * NTEAMS, parity ^= 1)
    {
        int t0 = tile * TPT;
        if (t0 > tokens - TPT) t0 = tokens - TPT;  // overlap tail (identical writes)
        if (t0 < 0) t0 = 0;

        // ---- compute phase: this warp scores its 8 codes for 6 tokens ----
        #pragma unroll
        for (int h = 0; h < NH; h++) {
            // front-batched x loads: lane owns 8 contiguous dims
            float4 xa[TPT], xb[TPT];
            const float4* xp0 = (const float4*)(x + (size_t)t0 * DFULL + h * DHD)
                                + (lane << 1);
            #pragma unroll
            for (int t = 0; t < TPT; t++) {
                xa[t] = xp0[t * 192];
                xb[t] = xp0[t * 192 + 1];
            }

            float acc[TPT][8];
            #pragma unroll
            for (int t = 0; t < TPT; t++)
                #pragma unroll
                for (int c = 0; c < 8; c++) acc[t][c] = 0.f;

            #pragma unroll
            for (int c = 0; c < 8; c++) {
                const float4* row = scb + (h * NC + half * 8 + c) * 64;
                float4 ka = row[2 * lane];
                float4 kb = row[2 * lane + 1];
                #pragma unroll
                for (int t = 0; t < TPT; t++) {
                    float a = acc[t][c];
                    a = fmaf(xa[t].x, ka.x, a);
                    a = fmaf(xa[t].y, ka.y, a);
                    a = fmaf(xa[t].z, ka.z, a);
                    a = fmaf(xa[t].w, ka.w, a);
                    a = fmaf(xb[t].x, kb.x, a);
                    a = fmaf(xb[t].y, kb.y, a);
                    a = fmaf(xb[t].z, kb.z, a);
                    a = fmaf(xb[t].w, kb.w, a);
                    acc[t][c] = a;
                }
            }

            // per token: split-exchange (9 shfl) + REDUX argmax over 8 codes
            #pragma unroll
            for (int t = 0; t < TPT; t++) {
                float w4[4];
                {
                    const bool up = (lane & 16) != 0;
                    #pragma unroll
                    for (int j = 0; j < 4; j++) {
                        float snd = up ? acc[t][j]     : acc[t][j + 4];
                        float kp  = up ? acc[t][j + 4] : acc[t][j];
                        w4[j] = kp + __shfl_xor_sync(FULLM, snd, 16);
                    }
                }
                float w2[2];
                {
                    const bool up = (lane & 8) != 0;
                    #pragma unroll
                    for (int j = 0; j < 2; j++) {
                        float s2 = up ? w4[j]     : w4[j + 2];
                        float k2 = up ? w4[j + 2] : w4[j];
                        w2[j] = k2 + __shfl_xor_sync(FULLM, s2, 8);
                    }
                }
                float w1;
                {
                    const bool up = (lane & 4) != 0;
                    float s1 = up ? w2[0] : w2[1];
                    float k1 = up ? w2[1] : w2[0];
                    w1 = k1 + __shfl_xor_sync(FULLM, s1, 4);
                }
                w1 += __shfl_xor_sync(FULLM, w1, 2);
                w1 += __shfl_xor_sync(FULLM, w1, 1);

                float sc = w1 - hn[h];
                unsigned u = fmono(sc);
                unsigned umax = __reduce_max_sync(FULLM, u);
                unsigned cand = (u == umax) ? (unsigned)gcode : 64u;
                unsigned gbest = __reduce_min_sync(FULLM, cand);
                // key: (score<<8) | (15 - idx): max key => max score, tie->min idx
                u64 key = ((u64)umax << 8) | (u64)(15u - gbest);
                if (lane == 0) keys[parity][warp][t][h] = key;
            }
        }

        asm volatile("bar.sync %0, 64;" :: "r"(bar_id) : "memory");

        // ---- finalize phase: this warp blends tokens [half*3, half*3+3) ----
        #pragma unroll
        for (int tt = 0; tt < 3; tt++) {
            const int t = half * 3 + tt;
            const long long tok = t0 + t;
            int pack = 0;
            #pragma unroll
            for (int h = 0; h < NH; h++) {
                u64 k0 = keys[parity][team * 2][t][h];
                u64 k1 = keys[parity][team * 2 + 1][t][h];
                u64 km = k0 > k1 ? k0 : k1;
                int bi = 15 - (int)(km & 0xFF);
                pack += bi << (4 * h);

                const float4* krow = scb + (h * NC + bi) * 64;
                float4 ka = krow[2 * lane];
                float4 kb = krow[2 * lane + 1];
                const float4* xr = (const float4*)(x + (size_t)tok * DFULL + h * DHD)
                                   + (lane << 1);
                float4 xA = xr[0];
                float4 xB = xr[1];
                float4 oa, ob;
                oa.x = fmaf(alpha, xA.x, beta * ka.x);
                oa.y = fmaf(alpha, xA.y, beta * ka.y);
                oa.z = fmaf(alpha, xA.z, beta * ka.z);
                oa.w = fmaf(alpha, xA.w, beta * ka.w);
                ob.x = fmaf(alpha, xB.x, beta * kb.x);
                ob.y = fmaf(alpha, xB.y, beta * kb.y);
                ob.z = fmaf(alpha, xB.z, beta * kb.z);
                ob.w = fmaf(alpha, xB.w, beta * kb.w);
                float4* op = (float4*)(out + (size_t)tok * DFULL + h * DHD)
                             + (lane << 1);
                op[0] = oa;
                op[1] = ob;
            }
            if (write_code && lane == 0) code_out[tok] = (float)pack;
        }
        // parity double-buffer removes the need for a post-read barrier.
    }
}

extern "C" void kernel_launch(void* const* d_in, const int* in_sizes, int n_in,
                              void* d_out, int out_size)
{
    const float* x      = (const float*)d_in[0];
    const float* kernel = (const float*)d_in[1];
    const float* alpha  = (const float*)d_in[2];
    float* out = (float*)d_out;

    const int tokens = in_sizes[0] / DFULL;
    const int nteamtiles = (tokens + TPT - 1) / TPT;

    const long long out_elems = (long long)tokens * DFULL;
    int write_code = (out_size >= out_elems + tokens) ? 1 : 0;
    float* code_out = out + out_elems;

    int grid = (nteamtiles + NTEAMS - 1) / NTEAMS;
    if (grid > 296) grid = 296;    // 2 blocks/SM

    rvq_kernel<<<grid, THREADS>>>(x, kernel, alpha, out, code_out,
                                  tokens, write_code, nteamtiles);
}

// round 6
// speedup vs baseline: 1.7472x; 1.2142x over previous
#include <cuda_runtime.h>
#include <cstdint>

// RVQ: x[B,S,768] f32, codebook[3,16,256] f32, alpha scalar.
// Per token, per head: argmax_c (x·k_c - 0.5||k_c||^2)  (== argmin sq-dist)
// out = alpha*x + (1-alpha)*k[best]; code = b0 + 16*b1 + 256*b2 (as f32).
//
// Scheme A skeleton: swizzled codebook LDS (conflict-free), front-batched x
// LDG, blend from live registers. TPW=4 tokens/warp, REDUX argmax.

#define NH   3
#define NC   16
#define DHD  256
#define DFULL 768
#define NF4  64             // float4 per code row (256 floats)
#define TPW  4              // tokens per warp
#define NWARPS 4
#define TPB  (TPW * NWARPS) // tokens per block tile (16)
#define FULLMASK 0xffffffffu

__device__ __forceinline__ int swz(int j) { return j ^ (j >> 3); }

__device__ __forceinline__ unsigned fmono(float f) {
    int b = __float_as_int(f);
    return (unsigned)(b ^ ((b >> 31) | 0x80000000));
}

__global__ void __launch_bounds__(128, 3) rvq_kernel(
    const float* __restrict__ x,
    const float* __restrict__ cb,
    const float* __restrict__ alphap,
    float* __restrict__ out,
    float* __restrict__ code_out,
    int tokens, int write_code, int ntiles)
{
    // Codebook in shared, XOR-swizzled within each 64-float4 row:
    // lane L reads swz(2L), swz(2L+1) -> per 8-lane phase the 4-bank groups
    // start at 0,8,16,24,4,12,20,28 — conflict-free.
    __shared__ float4 scb[NH * NC * NF4];   // 49152 bytes

    const int tid = threadIdx.x;
    {
        const float4* cbg = (const float4*)cb;
        #pragma unroll
        for (int g = tid; g < NH * NC * NF4; g += 128) {
            int r = g >> 6, j = g & 63;
            scb[(r << 6) + swz(j)] = cbg[g];
        }
    }
    __syncthreads();

    const int lane = tid & 31;
    const int warp = tid >> 5;
    const int cm   = (lane >> 1) & 15;   // code this lane owns after reduce

    // Per-lane half-norms of its mapped code, per head (one-time).
    float hn[NH];
    #pragma unroll
    for (int h = 0; h < NH; h++) {
        const float4* row = &scb[(h * NC + cm) << 6];
        float s = 0.f;
        #pragma unroll
        for (int j = 0; j < NF4; j++) {
            int jj = (j + cm) & 63;
            float4 k = row[swz(jj)];
            s = fmaf(k.x, k.x, s);
            s = fmaf(k.y, k.y, s);
            s = fmaf(k.z, k.z, s);
            s = fmaf(k.w, k.w, s);
        }
        hn[h] = 0.5f * s;
    }

    const float alpha = *alphap;
    const float beta  = 1.0f - alpha;

    for (int tile = blockIdx.x; tile < ntiles; tile += gridDim.x) {
        const long long t0 = (long long)tile * TPB + warp * TPW;
        int pack[TPW];
        #pragma unroll
        for (int t = 0; t < TPW; t++) pack[t] = 0;

        #pragma unroll
        for (int h = 0; h < NH; h++) {
            // Front-batched x loads: lane holds 8 contiguous dims of head h.
            float4 xa[TPW], xb[TPW];
            #pragma unroll
            for (int t = 0; t < TPW; t++) {
                if (t0 + t < tokens) {
                    const float4* xp =
                        (const float4*)(x + (size_t)(t0 + t) * DFULL + h * DHD)
                        + (lane << 1);
                    xa[t] = xp[0];
                    xb[t] = xp[1];
                } else {
                    xa[t] = make_float4(0.f, 0.f, 0.f, 0.f);
                    xb[t] = xa[t];
                }
            }

            // Partial dots: acc[t][c] = sum over this lane's 8 dims.
            float acc[TPW][NC];
            #pragma unroll
            for (int t = 0; t < TPW; t++)
                #pragma unroll
                for (int c = 0; c < NC; c++) acc[t][c] = 0.f;

            #pragma unroll
            for (int c = 0; c < NC; c++) {
                const float4* row = &scb[(h * NC + c) << 6];
                float4 ka = row[swz(2 * lane)];
                float4 kb = row[swz(2 * lane + 1)];
                #pragma unroll
                for (int t = 0; t < TPW; t++) {
                    float a = acc[t][c];
                    a = fmaf(xa[t].x, ka.x, a);
                    a = fmaf(xa[t].y, ka.y, a);
                    a = fmaf(xa[t].z, ka.z, a);
                    a = fmaf(xa[t].w, ka.w, a);
                    a = fmaf(xb[t].x, kb.x, a);
                    a = fmaf(xb[t].y, kb.y, a);
                    a = fmaf(xb[t].z, kb.z, a);
                    a = fmaf(xb[t].w, kb.w, a);
                    acc[t][c] = a;
                }
            }

            // Per token: multi-value split-exchange reduction (16 shfl),
            // then REDUX argmax (max score, tie -> min code).
            #pragma unroll
            for (int t = 0; t < TPW; t++) {
                float w8[8];
                {
                    const bool up = (lane & 16) != 0;
                    #pragma unroll
                    for (int j = 0; j < 8; j++) {
                        float snd = up ? acc[t][j]     : acc[t][j + 8];
                        float kp  = up ? acc[t][j + 8] : acc[t][j];
                        w8[j] = kp + __shfl_xor_sync(FULLMASK, snd, 16);
                    }
                }
                float w4[4];
                {
                    const bool up = (lane & 8) != 0;
                    #pragma unroll
                    for (int j = 0; j < 4; j++) {
                        float snd = up ? w8[j]     : w8[j + 4];
                        float kp  = up ? w8[j + 4] : w8[j];
                        w4[j] = kp + __shfl_xor_sync(FULLMASK, snd, 8);
                    }
                }
                float w2[2];
                {
                    const bool up = (lane & 4) != 0;
                    #pragma unroll
                    for (int j = 0; j < 2; j++) {
                        float snd = up ? w2[0] : 0.f; (void)snd;
                        float s2 = up ? w4[j]     : w4[j + 2];
                        float k2 = up ? w4[j + 2] : w4[j];
                        w2[j] = k2 + __shfl_xor_sync(FULLMASK, s2, 4);
                    }
                }
                float w1;
                {
                    const bool up = (lane & 2) != 0;
                    float s1 = up ? w2[0] : w2[1];
                    float k1 = up ? w2[1] : w2[0];
                    w1 = k1 + __shfl_xor_sync(FULLMASK, s1, 2);
                }
                w1 += __shfl_xor_sync(FULLMASK, w1, 1);

                float sc = w1 - hn[h];   // lane holds score of code cm
                unsigned u = fmono(sc);
                unsigned umax = __reduce_max_sync(FULLMASK, u);
                unsigned cand = (u == umax) ? (unsigned)cm : 64u;
                int bi = (int)__reduce_min_sync(FULLMASK, cand);
                pack[t] += bi << (4 * h);

                if (t0 + t < tokens) {
                    const float4* row = &scb[(h * NC + bi) << 6];
                    float4 ka = row[swz(2 * lane)];
                    float4 kb = row[swz(2 * lane + 1)];
                    float4 oa, ob;
                    oa.x = fmaf(alpha, xa[t].x, beta * ka.x);
                    oa.y = fmaf(alpha, xa[t].y, beta * ka.y);
                    oa.z = fmaf(alpha, xa[t].z, beta * ka.z);
                    oa.w = fmaf(alpha, xa[t].w, beta * ka.w);
                    ob.x = fmaf(alpha, xb[t].x, beta * kb.x);
                    ob.y = fmaf(alpha, xb[t].y, beta * kb.y);
                    ob.z = fmaf(alpha, xb[t].z, beta * kb.z);
                    ob.w = fmaf(alpha, xb[t].w, beta * kb.w);
                    float4* op =
                        (float4*)(out + (size_t)(t0 + t) * DFULL + h * DHD)
                        + (lane << 1);
                    op[0] = oa;
                    op[1] = ob;
                }
            }
        }

        if (write_code && lane == 0) {
            #pragma unroll
            for (int t = 0; t < TPW; t++)
                if (t0 + t < tokens)
                    code_out[t0 + t] = (float)pack[t];
        }
    }
}

extern "C" void kernel_launch(void* const* d_in, const int* in_sizes, int n_in,
                              void* d_out, int out_size)
{
    const float* x      = (const float*)d_in[0];
    const float* kernel = (const float*)d_in[1];
    const float* alpha  = (const float*)d_in[2];
    float* out = (float*)d_out;

    const int tokens = in_sizes[0] / DFULL;        // B*S
    const int ntiles = (tokens + TPB - 1) / TPB;

    const long long out_elems = (long long)tokens * DFULL;
    int write_code = (out_size >= out_elems + tokens) ? 1 : 0;
    float* code_out = out + out_elems;

    int grid = ntiles < 444 ? ntiles : 444;   // 3 resident blocks/SM * 148
    rvq_kernel<<<grid, 128>>>(x, kernel, alpha, out, code_out,
                              tokens, write_code, ntiles);
}